// round 4
// baseline (speedup 1.0000x reference)
#include <cuda_runtime.h>
#include <cuda_bf16.h>
#include <float.h>

// VectorQuantizer: out[n] = argmin_k ||x_n - e_k||^2
//                        = argmin_k ( e_sq[k] - 2 * <x_n, e_k> )
// N=32768, K=8192, D=256 fp32.
//
// HYPOTHESIS UNDER TEST: harness output dtype is float32 (indices compared as
// floats). Writing int32 bits yields denormals ~= 0 -> rel_err exactly 1.0,
// matching all prior rounds. So we write (float)index.
//
// Inputs identified by size: `inputs` (N rows) is the LARGER buffer,
// `embedding` (K rows) the smaller — independent of argument order/out_size.

#define DD 256
#define BN 64
#define BK 64
#define BD 32
#define SPAD 36            // smem row stride in floats (16B-aligned rows)
#define NT 256

#define KMAX 8192
__device__ float g_esq[KMAX];

// ---------------------------------------------------------------------------
// e_sq[k] = sum_d e[k][d]^2
// ---------------------------------------------------------------------------
__global__ void esq_kernel(const float* __restrict__ e, int K) {
    int k = blockIdx.x * blockDim.x + threadIdx.x;
    if (k >= K) return;
    const float* row = e + (size_t)k * DD;
    float s = 0.0f;
#pragma unroll 8
    for (int d = 0; d < DD; d++) s += row[d] * row[d];
    g_esq[k] = s;
}

// ---------------------------------------------------------------------------
// Main kernel: one CTA handles 64 input rows against all K codes.
// 16x16 threads; thread (ty,tx) owns rows ty*4..ty*4+3, cols {tx,tx+16,tx+32,tx+48}.
// ---------------------------------------------------------------------------
__global__ __launch_bounds__(NT)
void vq_argmin_kernel(const float* __restrict__ x,
                      const float* __restrict__ e,
                      float* __restrict__ out,   // float32 indices
                      int K) {
    __shared__ __align__(16) float sx[BN][SPAD];
    __shared__ __align__(16) float se[BK][SPAD];
    __shared__ float red_d[16][16];
    __shared__ int   red_i[16][16];

    const int tid  = threadIdx.x;
    const int ty   = tid >> 4;
    const int tx   = tid & 15;
    const int row0 = blockIdx.x * BN;

    float mind[4];
    int   mini[4];
#pragma unroll
    for (int i = 0; i < 4; i++) { mind[i] = FLT_MAX; mini[i] = 0; }

    for (int kt = 0; kt < K; kt += BK) {
        float acc[4][4];
#pragma unroll
        for (int i = 0; i < 4; i++)
#pragma unroll
            for (int j = 0; j < 4; j++) acc[i][j] = 0.0f;

        for (int dc = 0; dc < DD; dc += BD) {
            __syncthreads();   // previous chunk's reads done before overwrite

            // Stage x chunk: 64 rows x 32 floats = 512 float4, 2 per thread.
#pragma unroll
            for (int t = 0; t < 2; t++) {
                int idx = tid + t * NT;
                int r   = idx >> 3;
                int c4  = idx & 7;
                float4 v = *(const float4*)(x + (size_t)(row0 + r) * DD + dc + c4 * 4);
                *(float4*)&sx[r][c4 * 4] = v;
            }
            // Stage e chunk likewise.
#pragma unroll
            for (int t = 0; t < 2; t++) {
                int idx = tid + t * NT;
                int r   = idx >> 3;
                int c4  = idx & 7;
                float4 v = *(const float4*)(e + (size_t)(kt + r) * DD + dc + c4 * 4);
                *(float4*)&se[r][c4 * 4] = v;
            }
            __syncthreads();

#pragma unroll
            for (int d = 0; d < BD; d += 4) {
                float4 xa[4], eb[4];
#pragma unroll
                for (int i = 0; i < 4; i++)
                    xa[i] = *(const float4*)&sx[ty * 4 + i][d];
#pragma unroll
                for (int j = 0; j < 4; j++)
                    eb[j] = *(const float4*)&se[tx + 16 * j][d];
#pragma unroll
                for (int i = 0; i < 4; i++)
#pragma unroll
                    for (int j = 0; j < 4; j++) {
                        acc[i][j] = fmaf(xa[i].x, eb[j].x, acc[i][j]);
                        acc[i][j] = fmaf(xa[i].y, eb[j].y, acc[i][j]);
                        acc[i][j] = fmaf(xa[i].z, eb[j].z, acc[i][j]);
                        acc[i][j] = fmaf(xa[i].w, eb[j].w, acc[i][j]);
                    }
            }
        }

        // Fused argmin epilogue: dist = e_sq[k] - 2*cross.
#pragma unroll
        for (int j = 0; j < 4; j++) {
            int   kidx = kt + tx + 16 * j;
            float es   = g_esq[kidx];
#pragma unroll
            for (int i = 0; i < 4; i++) {
                float dist = fmaf(-2.0f, acc[i][j], es);
                // strict < keeps earliest k (k strictly ascends per thread)
                if (dist < mind[i]) { mind[i] = dist; mini[i] = kidx; }
            }
        }
    }

    // Final reduction across the 16 tx-lanes per row (tie -> smaller index,
    // matching jnp.argmin first-occurrence semantics).
#pragma unroll
    for (int i = 0; i < 4; i++) {
        __syncthreads();
        red_d[ty][tx] = mind[i];
        red_i[ty][tx] = mini[i];
        __syncthreads();
        if (tx == 0) {
            float bd = red_d[ty][0];
            int   bi = red_i[ty][0];
#pragma unroll
            for (int t = 1; t < 16; t++) {
                float d2 = red_d[ty][t];
                int   i2 = red_i[ty][t];
                if (d2 < bd || (d2 == bd && i2 < bi)) { bd = d2; bi = i2; }
            }
            out[row0 + ty * 4 + i] = (float)bi;   // FLOAT32 output
        }
    }
}

// ---------------------------------------------------------------------------
// Launch
// ---------------------------------------------------------------------------
extern "C" void kernel_launch(void* const* d_in, const int* in_sizes, int n_in,
                              void* d_out, int out_size) {
    // `inputs` is the larger buffer (N=32768 rows vs K=8192 rows).
    const float* x;
    const float* e;
    int N, K;
    if (in_sizes[0] >= in_sizes[1]) {
        x = (const float*)d_in[0]; N = in_sizes[0] / DD;
        e = (const float*)d_in[1]; K = in_sizes[1] / DD;
    } else {
        x = (const float*)d_in[1]; N = in_sizes[1] / DD;
        e = (const float*)d_in[0]; K = in_sizes[0] / DD;
    }
    float* out = (float*)d_out;

    esq_kernel<<<(K + 255) / 256, 256>>>(e, K);
    vq_argmin_kernel<<<N / BN, NT>>>(x, e, out, K);
}

// round 7
// speedup vs baseline: 2.7788x; 2.7788x over previous
#include <cuda_runtime.h>
#include <cuda_bf16.h>
#include <float.h>
#include <stdint.h>

// VectorQuantizer via mma.sync (bf16, fp32 accum) + fused argmin.
// out[n] = (float) argmin_k ( e_sq[k] - 2 * <x_n, e_k> )
// cross computed with 4-product bf16 split: xh*eh + xh*el + xl*eh + xl*el.
// B operand loaded with NON-trans ldmatrix: e stored [code][k] (k contiguous)
// IS col-major B for mma row.col; .trans was the R6 bug.

#define DD      256
#define NMAX    32768
#define KMAX    8192

#define TILE_M  128       // rows per CTA
#define TILE_NC 64        // codes per K-tile
#define BD      64        // depth per chunk
#define NT      256       // 8 warps

// dynamic smem layout (bytes)
#define XSTRIDE       264                      // bf16 per x row (256 + 8 pad)
#define ESTRIDE       72                       // bf16 per e row (64 + 8 pad)
#define XSPLIT_BYTES  (TILE_M * XSTRIDE * 2)   // 67584
#define SM_X          0                        // [split][128][264]
#define ESPLIT_BYTES  (TILE_NC * ESTRIDE * 2)  // 9216
#define EBUF_BYTES    (2 * ESPLIT_BYTES)       // 18432 (hi+lo)
#define SM_E          (2 * XSPLIT_BYTES)       // ring of 2 bufs
#define SMEM_BYTES    (SM_E + 2 * EBUF_BYTES)  // 172032

__device__ float         g_esq[KMAX];
__device__ __nv_bfloat16 g_xh[(size_t)NMAX * DD];
__device__ __nv_bfloat16 g_xl[(size_t)NMAX * DD];
__device__ __nv_bfloat16 g_eh[(size_t)KMAX * DD];
__device__ __nv_bfloat16 g_el[(size_t)KMAX * DD];

// ---------------------------------------------------------------------------
// helpers
// ---------------------------------------------------------------------------
__device__ __forceinline__ uint32_t smem_u32(const void* p) {
    uint32_t a;
    asm("{ .reg .u64 t; cvta.to.shared.u64 t, %1; cvt.u32.u64 %0, t; }"
        : "=r"(a) : "l"(p));
    return a;
}
__device__ __forceinline__ void ldsm_x4(uint32_t* r, uint32_t addr) {
    asm volatile("ldmatrix.sync.aligned.m8n8.x4.shared.b16 {%0,%1,%2,%3}, [%4];"
                 : "=r"(r[0]), "=r"(r[1]), "=r"(r[2]), "=r"(r[3]) : "r"(addr));
}
__device__ __forceinline__ void mma_bf16(float* d, const uint32_t* a, uint32_t b0, uint32_t b1) {
    asm volatile(
        "mma.sync.aligned.m16n8k16.row.col.f32.bf16.bf16.f32 "
        "{%0,%1,%2,%3}, {%4,%5,%6,%7}, {%8,%9}, {%0,%1,%2,%3};"
        : "+f"(d[0]), "+f"(d[1]), "+f"(d[2]), "+f"(d[3])
        : "r"(a[0]), "r"(a[1]), "r"(a[2]), "r"(a[3]), "r"(b0), "r"(b1));
}
__device__ __forceinline__ void cp16(uint32_t dst, const void* src) {
    asm volatile("cp.async.cg.shared.global [%0], [%1], 16;"
                 :: "r"(dst), "l"(__cvta_generic_to_global(src)) : "memory");
}

// ---------------------------------------------------------------------------
// precompute kernels
// ---------------------------------------------------------------------------
__global__ void esq_kernel(const float* __restrict__ e, int K) {
    int k = blockIdx.x * blockDim.x + threadIdx.x;
    if (k >= K) return;
    const float* row = e + (size_t)k * DD;
    float s = 0.0f;
#pragma unroll 8
    for (int d = 0; d < DD; d++) s += row[d] * row[d];
    g_esq[k] = s;
}
__global__ void split_kernel(const float* __restrict__ src,
                             __nv_bfloat16* __restrict__ hi,
                             __nv_bfloat16* __restrict__ lo, int n) {
    int i = blockIdx.x * blockDim.x + threadIdx.x;
    if (i >= n) return;
    float v = src[i];
    __nv_bfloat16 h = __float2bfloat16(v);
    hi[i] = h;
    lo[i] = __float2bfloat16(v - __bfloat162float(h));
}

// ---------------------------------------------------------------------------
// main kernel
// ---------------------------------------------------------------------------
__global__ __launch_bounds__(NT, 1)
void vq_mma_kernel(float* __restrict__ out, int N, int K) {
    extern __shared__ __align__(128) char smem[];
    __shared__ float sd[2][TILE_M];
    __shared__ int   si[2][TILE_M];

    const int tid  = threadIdx.x;
    const int wid  = tid >> 5;
    const int lane = tid & 31;
    const int gr   = lane >> 2;       // 0..7
    const int tc   = lane & 3;        // 0..3
    const int mw   = wid >> 1;        // 0..3  (M slice: mw*32)
    const int nw   = wid & 1;         // 0..1  (N slice: nw*32)
    const int row0 = blockIdx.x * TILE_M;

    const uint32_t smb  = smem_u32(smem);
    const uint32_t smX  = smb + SM_X;
    const uint32_t smE  = smb + SM_E;

    // ---- load resident x tiles (hi/lo), row-major with padded stride ----
    {
        const uint4* xh4 = (const uint4*)g_xh;
        const uint4* xl4 = (const uint4*)g_xl;
#pragma unroll
        for (int t = 0; t < 16; t++) {
            int idx = tid + t * NT;          // 0..4095
            int r   = idx >> 5;              // row
            int g16 = idx & 31;              // 16B granule (32 per 512B row)
            size_t g = (size_t)(row0 + r) * 32 + g16;
            uint32_t off = (uint32_t)r * (XSTRIDE * 2) + (uint32_t)g16 * 16;
            *(uint4*)(smem + SM_X + off)                = xh4[g];
            *(uint4*)(smem + SM_X + XSPLIT_BYTES + off) = xl4[g];
        }
    }

    // ---- lane-dependent ldmatrix base offsets ----
    // A: row = R0 + (lane&15), kcol byte += (lane&16)      (k halves 0/8)
    const uint32_t a_lane = (uint32_t)(lane & 15) * (XSTRIDE * 2) + (uint32_t)(lane & 16);
    // B: row = C0 + (lane&7) + ((lane&16)>>1), kcol byte += (lane&8)*2
    const uint32_t b_lane = ((uint32_t)((lane & 7) + ((lane & 16) >> 1))) * (ESTRIDE * 2)
                          + (uint32_t)((lane & 8) << 1);

    const int n_tiles = K / TILE_NC;
    const int G       = n_tiles * (DD / BD);      // chunks

    // per-lane running argmin: 4 row-slots (mt*2 + half)
    float best_d[4];
    int   best_i[4];
#pragma unroll
    for (int s = 0; s < 4; s++) { best_d[s] = FLT_MAX; best_i[s] = 0; }

    float acc[2][4][4];

    // ---- e-chunk loader (cp.async, 4 x 16B per thread) ----
    auto issue_load = [&](int g) {
        int c   = g & 3;
        int kt0 = (g >> 2) * TILE_NC;
        uint32_t dbase = smE + (uint32_t)(g & 1) * EBUF_BYTES;
#pragma unroll
        for (int t = 0; t < 4; t++) {
            int idx = tid + t * NT;          // 0..1023
            int sp  = idx >> 9;              // split
            int rem = idx & 511;
            int j   = rem >> 3;              // code row 0..63
            int g16 = rem & 7;               // 16B granule
            const __nv_bfloat16* src =
                (sp ? g_el : g_eh) + (size_t)(kt0 + j) * DD + c * BD + g16 * 8;
            uint32_t dst = dbase + (uint32_t)sp * ESPLIT_BYTES
                         + (uint32_t)j * (ESTRIDE * 2) + (uint32_t)g16 * 16;
            cp16(dst, src);
        }
        asm volatile("cp.async.commit_group;" ::: "memory");
    };

    issue_load(0);

    for (int g = 0; g < G; g++) {
        const int c   = g & 3;
        const int kt  = g >> 2;
        const int kt0 = kt * TILE_NC;

        if (g + 1 < G) {
            issue_load(g + 1);
            asm volatile("cp.async.wait_group 1;" ::: "memory");
        } else {
            asm volatile("cp.async.wait_group 0;" ::: "memory");
        }
        __syncthreads();   // buffer (g&1) ready for all warps; x visible (iter 0)

        if (c == 0) {
#pragma unroll
            for (int mt = 0; mt < 2; mt++)
#pragma unroll
                for (int n = 0; n < 4; n++)
#pragma unroll
                    for (int v = 0; v < 4; v++) acc[mt][n][v] = 0.0f;
        }

        const uint32_t eb = smE + (uint32_t)(g & 1) * EBUF_BYTES;

#pragma unroll
        for (int ks = 0; ks < 4; ks++) {
            // A fragments (hi/lo) for 2 m-tiles
            uint32_t ah[2][4], al[2][4];
#pragma unroll
            for (int mt = 0; mt < 2; mt++) {
                uint32_t base = smX + a_lane
                              + (uint32_t)(mw * 32 + mt * 16) * (XSTRIDE * 2)
                              + (uint32_t)(c * BD + ks * 16) * 2;
                ldsm_x4(ah[mt], base);
                ldsm_x4(al[mt], base + XSPLIT_BYTES);
            }
            // B fragments (hi/lo): NON-trans x4 per split -> 4 n-tiles
            // (e stored [code][k], k contiguous == col-major B for row.col mma)
            uint32_t bh[2][4], bl[2][4];
#pragma unroll
            for (int np = 0; np < 2; np++) {
                uint32_t base = eb + b_lane
                              + (uint32_t)(nw * 32 + np * 16) * (ESTRIDE * 2)
                              + (uint32_t)(ks * 16) * 2;
                ldsm_x4(bh[np], base);
                ldsm_x4(bl[np], base + ESPLIT_BYTES);
            }
#pragma unroll
            for (int mt = 0; mt < 2; mt++)
#pragma unroll
                for (int n = 0; n < 4; n++) {
                    uint32_t b0h = bh[n >> 1][(n & 1) * 2], b1h = bh[n >> 1][(n & 1) * 2 + 1];
                    uint32_t b0l = bl[n >> 1][(n & 1) * 2], b1l = bl[n >> 1][(n & 1) * 2 + 1];
                    mma_bf16(acc[mt][n], ah[mt], b0h, b1h);   // hi*hi
                    mma_bf16(acc[mt][n], ah[mt], b0l, b1l);   // hi*lo
                    mma_bf16(acc[mt][n], al[mt], b0h, b1h);   // lo*hi
                    mma_bf16(acc[mt][n], al[mt], b0l, b1l);   // lo*lo
                }
        }

        // ---- per-tile argmin epilogue (registers only) ----
        if (c == 3) {
            const int kb = kt0 + nw * 32;
#pragma unroll
            for (int n = 0; n < 4; n++) {
                const int c0 = kb + n * 8 + 2 * tc;
                float2 es = *(const float2*)&g_esq[c0];
#pragma unroll
                for (int mt = 0; mt < 2; mt++) {
                    float d0 = fmaf(-2.0f, acc[mt][n][0], es.x);
                    float d1 = fmaf(-2.0f, acc[mt][n][1], es.y);
                    float d2 = fmaf(-2.0f, acc[mt][n][2], es.x);
                    float d3 = fmaf(-2.0f, acc[mt][n][3], es.y);
                    int s0 = mt * 2, s1 = mt * 2 + 1;
                    if (d0 < best_d[s0]) { best_d[s0] = d0; best_i[s0] = c0; }
                    if (d1 < best_d[s0]) { best_d[s0] = d1; best_i[s0] = c0 + 1; }
                    if (d2 < best_d[s1]) { best_d[s1] = d2; best_i[s1] = c0; }
                    if (d3 < best_d[s1]) { best_d[s1] = d3; best_i[s1] = c0 + 1; }
                }
            }
        }
        __syncthreads();   // reads of buffer (g&1) done before it is refilled
    }

    // ---- reduce across the 4 tc-lanes of each row group ----
#pragma unroll
    for (int s = 0; s < 4; s++) {
        float d = best_d[s];
        int   i = best_i[s];
#pragma unroll
        for (int off = 1; off <= 2; off <<= 1) {
            float od = __shfl_xor_sync(0xffffffffu, d, off);
            int   oi = __shfl_xor_sync(0xffffffffu, i, off);
            if (od < d || (od == d && oi < i)) { d = od; i = oi; }
        }
        if (tc == 0) {
            int row_local = mw * 32 + (s >> 1) * 16 + (s & 1) * 8 + gr;
            sd[nw][row_local] = d;
            si[nw][row_local] = i;
        }
    }
    __syncthreads();

    // ---- combine the two N-warps, write float32 indices ----
    if (tid < TILE_M) {
        float d0 = sd[0][tid], d1 = sd[1][tid];
        int   i0 = si[0][tid], i1 = si[1][tid];
        int best = (d1 < d0 || (d1 == d0 && i1 < i0)) ? i1 : i0;
        out[row0 + tid] = (float)best;
    }
}

// ---------------------------------------------------------------------------
// launch
// ---------------------------------------------------------------------------
extern "C" void kernel_launch(void* const* d_in, const int* in_sizes, int n_in,
                              void* d_out, int out_size) {
    // `inputs` is the larger buffer (N=32768 rows vs K=8192 rows).
    const float* x;
    const float* e;
    int N, K;
    if (in_sizes[0] >= in_sizes[1]) {
        x = (const float*)d_in[0]; N = in_sizes[0] / DD;
        e = (const float*)d_in[1]; K = in_sizes[1] / DD;
    } else {
        x = (const float*)d_in[1]; N = in_sizes[1] / DD;
        e = (const float*)d_in[0]; K = in_sizes[0] / DD;
    }
    float* out = (float*)d_out;

    __nv_bfloat16 *xh, *xl, *eh, *el;
    cudaGetSymbolAddress((void**)&xh, g_xh);
    cudaGetSymbolAddress((void**)&xl, g_xl);
    cudaGetSymbolAddress((void**)&eh, g_eh);
    cudaGetSymbolAddress((void**)&el, g_el);

    const int nx = N * DD, ne = K * DD;
    split_kernel<<<(nx + 255) / 256, 256>>>(x, xh, xl, nx);
    split_kernel<<<(ne + 255) / 256, 256>>>(e, eh, el, ne);
    esq_kernel<<<(K + 255) / 256, 256>>>(e, K);

    cudaFuncSetAttribute(vq_mma_kernel,
                         cudaFuncAttributeMaxDynamicSharedMemorySize, SMEM_BYTES);
    vq_mma_kernel<<<N / TILE_M, NT, SMEM_BYTES>>>(out, N, K);
}

// round 8
// speedup vs baseline: 3.1381x; 1.1293x over previous
#include <cuda_runtime.h>
#include <cuda_fp16.h>
#include <float.h>
#include <stdint.h>

// VectorQuantizer via mma.sync (fp16, fp32 accum) + fused argmin.
// out[n] = (float) argmin_k ( e_sq[k] - 2 * <x_n, e_k> )
// cross via 3-product fp16 split (Ootomo-style): xh*eh + xh*el + xl*eh.
// fp16 split residual ~2^-22 (better than R7's bf16 4-product, which flipped
// zero argmins), at 3/4 the tensor work.
// TILE_M=64 / 104.4KB smem -> 2 CTAs/SM for sync/load overlap.

#define DD      256
#define NMAX    32768
#define KMAX    8192

#define TILE_M  64        // rows per CTA
#define TILE_NC 64        // codes per K-tile
#define BD      64        // depth per chunk
#define NT      128       // 4 warps: 2 (M) x 2 (N), 32x32 warp tiles

// dynamic smem layout (bytes)
#define XSTRIDE       264                      // fp16 per x row (256 + 8 pad)
#define ESTRIDE       72                       // fp16 per e row (64 + 8 pad)
#define XSPLIT_BYTES  (TILE_M * XSTRIDE * 2)   // 33792
#define SM_X          0                        // [split][64][264]
#define ESPLIT_BYTES  (TILE_NC * ESTRIDE * 2)  // 9216
#define EBUF_BYTES    (2 * ESPLIT_BYTES)       // 18432 (hi+lo)
#define SM_E          (2 * XSPLIT_BYTES)       // ring of 2 bufs
#define SMEM_BYTES    (SM_E + 2 * EBUF_BYTES)  // 104448

__device__ float  g_esq[KMAX];
__device__ __half g_xh[(size_t)NMAX * DD];
__device__ __half g_xl[(size_t)NMAX * DD];
__device__ __half g_eh[(size_t)KMAX * DD];
__device__ __half g_el[(size_t)KMAX * DD];

// ---------------------------------------------------------------------------
// helpers
// ---------------------------------------------------------------------------
__device__ __forceinline__ uint32_t smem_u32(const void* p) {
    uint32_t a;
    asm("{ .reg .u64 t; cvta.to.shared.u64 t, %1; cvt.u32.u64 %0, t; }"
        : "=r"(a) : "l"(p));
    return a;
}
__device__ __forceinline__ void ldsm_x4(uint32_t* r, uint32_t addr) {
    asm volatile("ldmatrix.sync.aligned.m8n8.x4.shared.b16 {%0,%1,%2,%3}, [%4];"
                 : "=r"(r[0]), "=r"(r[1]), "=r"(r[2]), "=r"(r[3]) : "r"(addr));
}
__device__ __forceinline__ void mma_f16(float* d, const uint32_t* a, uint32_t b0, uint32_t b1) {
    asm volatile(
        "mma.sync.aligned.m16n8k16.row.col.f32.f16.f16.f32 "
        "{%0,%1,%2,%3}, {%4,%5,%6,%7}, {%8,%9}, {%0,%1,%2,%3};"
        : "+f"(d[0]), "+f"(d[1]), "+f"(d[2]), "+f"(d[3])
        : "r"(a[0]), "r"(a[1]), "r"(a[2]), "r"(a[3]), "r"(b0), "r"(b1));
}
__device__ __forceinline__ void cp16(uint32_t dst, const void* src) {
    asm volatile("cp.async.cg.shared.global [%0], [%1], 16;"
                 :: "r"(dst), "l"(__cvta_generic_to_global(src)) : "memory");
}

// ---------------------------------------------------------------------------
// precompute kernels
// ---------------------------------------------------------------------------
__global__ void esq_kernel(const float* __restrict__ e, int K) {
    int k = blockIdx.x * blockDim.x + threadIdx.x;
    if (k >= K) return;
    const float* row = e + (size_t)k * DD;
    float s = 0.0f;
#pragma unroll 8
    for (int d = 0; d < DD; d++) s += row[d] * row[d];
    g_esq[k] = s;
}
__global__ void split_kernel(const float* __restrict__ src,
                             __half* __restrict__ hi,
                             __half* __restrict__ lo, int n) {
    int i = blockIdx.x * blockDim.x + threadIdx.x;
    if (i >= n) return;
    float v = src[i];
    __half h = __float2half(v);
    hi[i] = h;
    lo[i] = __float2half(v - __half2float(h));
}

// ---------------------------------------------------------------------------
// main kernel: 4 warps, 2 CTAs/SM
// ---------------------------------------------------------------------------
__global__ __launch_bounds__(NT, 2)
void vq_mma_kernel(float* __restrict__ out, int N, int K) {
    extern __shared__ __align__(128) char smem[];
    __shared__ float sd[2][TILE_M];
    __shared__ int   si[2][TILE_M];

    const int tid  = threadIdx.x;
    const int wid  = tid >> 5;
    const int lane = tid & 31;
    const int gr   = lane >> 2;       // 0..7
    const int tc   = lane & 3;        // 0..3
    const int mw   = wid >> 1;        // 0..1  (M slice: mw*32)
    const int nw   = wid & 1;         // 0..1  (N slice: nw*32)
    const int row0 = blockIdx.x * TILE_M;

    const uint32_t smb = smem_u32(smem);
    const uint32_t smX = smb + SM_X;
    const uint32_t smE = smb + SM_E;

    // ---- load resident x tiles (hi/lo), row-major with padded stride ----
    {
        const uint4* xh4 = (const uint4*)g_xh;
        const uint4* xl4 = (const uint4*)g_xl;
#pragma unroll
        for (int t = 0; t < 16; t++) {
            int idx = tid + t * NT;          // 0..2047
            int r   = idx >> 5;              // row 0..63
            int g16 = idx & 31;              // 16B granule (32 per 512B row)
            size_t g = (size_t)(row0 + r) * 32 + g16;
            uint32_t off = (uint32_t)r * (XSTRIDE * 2) + (uint32_t)g16 * 16;
            *(uint4*)(smem + SM_X + off)                = xh4[g];
            *(uint4*)(smem + SM_X + XSPLIT_BYTES + off) = xl4[g];
        }
    }

    // ---- lane-dependent ldmatrix base offsets ----
    const uint32_t a_lane = (uint32_t)(lane & 15) * (XSTRIDE * 2) + (uint32_t)(lane & 16);
    const uint32_t b_lane = ((uint32_t)((lane & 7) + ((lane & 16) >> 1))) * (ESTRIDE * 2)
                          + (uint32_t)((lane & 8) << 1);

    const int n_tiles = K / TILE_NC;
    const int G       = n_tiles * (DD / BD);      // chunks

    // per-lane running argmin: 4 row-slots (mt*2 + half)
    float best_d[4];
    int   best_i[4];
#pragma unroll
    for (int s = 0; s < 4; s++) { best_d[s] = FLT_MAX; best_i[s] = 0; }

    float acc[2][4][4];

    // ---- e-chunk loader (cp.async, 8 x 16B per thread) ----
    auto issue_load = [&](int g) {
        int c   = g & 3;
        int kt0 = (g >> 2) * TILE_NC;
        uint32_t dbase = smE + (uint32_t)(g & 1) * EBUF_BYTES;
#pragma unroll
        for (int t = 0; t < 8; t++) {
            int idx = tid + t * NT;          // 0..1023
            int sp  = idx >> 9;              // split
            int rem = idx & 511;
            int j   = rem >> 3;              // code row 0..63
            int g16 = rem & 7;               // 16B granule
            const __half* src =
                (sp ? g_el : g_eh) + (size_t)(kt0 + j) * DD + c * BD + g16 * 8;
            uint32_t dst = dbase + (uint32_t)sp * ESPLIT_BYTES
                         + (uint32_t)j * (ESTRIDE * 2) + (uint32_t)g16 * 16;
            cp16(dst, src);
        }
        asm volatile("cp.async.commit_group;" ::: "memory");
    };

    issue_load(0);

    for (int g = 0; g < G; g++) {
        const int c   = g & 3;
        const int kt  = g >> 2;
        const int kt0 = kt * TILE_NC;

        if (g + 1 < G) {
            issue_load(g + 1);
            asm volatile("cp.async.wait_group 1;" ::: "memory");
        } else {
            asm volatile("cp.async.wait_group 0;" ::: "memory");
        }
        __syncthreads();   // buffer (g&1) ready; x tile visible (iter 0)

        if (c == 0) {
#pragma unroll
            for (int mt = 0; mt < 2; mt++)
#pragma unroll
                for (int n = 0; n < 4; n++)
#pragma unroll
                    for (int v = 0; v < 4; v++) acc[mt][n][v] = 0.0f;
        }

        const uint32_t eb = smE + (uint32_t)(g & 1) * EBUF_BYTES;

#pragma unroll
        for (int ks = 0; ks < 4; ks++) {
            // A fragments (hi/lo) for 2 m-tiles
            uint32_t ah[2][4], al[2][4];
#pragma unroll
            for (int mt = 0; mt < 2; mt++) {
                uint32_t base = smX + a_lane
                              + (uint32_t)(mw * 32 + mt * 16) * (XSTRIDE * 2)
                              + (uint32_t)(c * BD + ks * 16) * 2;
                ldsm_x4(ah[mt], base);
                ldsm_x4(al[mt], base + XSPLIT_BYTES);
            }
            // B fragments (hi/lo): NON-trans x4 per split -> 4 n-tiles
            uint32_t bh[2][4], bl[2][4];
#pragma unroll
            for (int np = 0; np < 2; np++) {
                uint32_t base = eb + b_lane
                              + (uint32_t)(nw * 32 + np * 16) * (ESTRIDE * 2)
                              + (uint32_t)(ks * 16) * 2;
                ldsm_x4(bh[np], base);
                ldsm_x4(bl[np], base + ESPLIT_BYTES);
            }
#pragma unroll
            for (int mt = 0; mt < 2; mt++)
#pragma unroll
                for (int n = 0; n < 4; n++) {
                    uint32_t b0h = bh[n >> 1][(n & 1) * 2], b1h = bh[n >> 1][(n & 1) * 2 + 1];
                    uint32_t b0l = bl[n >> 1][(n & 1) * 2], b1l = bl[n >> 1][(n & 1) * 2 + 1];
                    mma_f16(acc[mt][n], ah[mt], b0h, b1h);   // hi*hi
                    mma_f16(acc[mt][n], ah[mt], b0l, b1l);   // hi*lo
                    mma_f16(acc[mt][n], al[mt], b0h, b1h);   // lo*hi
                }
        }

        // ---- per-tile argmin epilogue (registers only) ----
        if (c == 3) {
            const int kb = kt0 + nw * 32;
#pragma unroll
            for (int n = 0; n < 4; n++) {
                const int c0 = kb + n * 8 + 2 * tc;
                float2 es = *(const float2*)&g_esq[c0];
#pragma unroll
                for (int mt = 0; mt < 2; mt++) {
                    float d0 = fmaf(-2.0f, acc[mt][n][0], es.x);
                    float d1 = fmaf(-2.0f, acc[mt][n][1], es.y);
                    float d2 = fmaf(-2.0f, acc[mt][n][2], es.x);
                    float d3 = fmaf(-2.0f, acc[mt][n][3], es.y);
                    int s0 = mt * 2, s1 = mt * 2 + 1;
                    if (d0 < best_d[s0]) { best_d[s0] = d0; best_i[s0] = c0; }
                    if (d1 < best_d[s0]) { best_d[s0] = d1; best_i[s0] = c0 + 1; }
                    if (d2 < best_d[s1]) { best_d[s1] = d2; best_i[s1] = c0; }
                    if (d3 < best_d[s1]) { best_d[s1] = d3; best_i[s1] = c0 + 1; }
                }
            }
        }
        __syncthreads();   // reads of buffer (g&1) done before refill
    }

    // ---- reduce across the 4 tc-lanes of each row group ----
#pragma unroll
    for (int s = 0; s < 4; s++) {
        float d = best_d[s];
        int   i = best_i[s];
#pragma unroll
        for (int off = 1; off <= 2; off <<= 1) {
            float od = __shfl_xor_sync(0xffffffffu, d, off);
            int   oi = __shfl_xor_sync(0xffffffffu, i, off);
            if (od < d || (od == d && oi < i)) { d = od; i = oi; }
        }
        if (tc == 0) {
            int row_local = mw * 32 + (s >> 1) * 16 + (s & 1) * 8 + gr;
            sd[nw][row_local] = d;
            si[nw][row_local] = i;
        }
    }
    __syncthreads();

    // ---- combine the two N-warps, write float32 indices ----
    if (tid < TILE_M) {
        float d0 = sd[0][tid], d1 = sd[1][tid];
        int   i0 = si[0][tid], i1 = si[1][tid];
        int best = (d1 < d0 || (d1 == d0 && i1 < i0)) ? i1 : i0;
        out[row0 + tid] = (float)best;
    }
}

// ---------------------------------------------------------------------------
// launch
// ---------------------------------------------------------------------------
extern "C" void kernel_launch(void* const* d_in, const int* in_sizes, int n_in,
                              void* d_out, int out_size) {
    // `inputs` is the larger buffer (N=32768 rows vs K=8192 rows).
    const float* x;
    const float* e;
    int N, K;
    if (in_sizes[0] >= in_sizes[1]) {
        x = (const float*)d_in[0]; N = in_sizes[0] / DD;
        e = (const float*)d_in[1]; K = in_sizes[1] / DD;
    } else {
        x = (const float*)d_in[1]; N = in_sizes[1] / DD;
        e = (const float*)d_in[0]; K = in_sizes[0] / DD;
    }
    float* out = (float*)d_out;

    __half *xh, *xl, *eh, *el;
    cudaGetSymbolAddress((void**)&xh, g_xh);
    cudaGetSymbolAddress((void**)&xl, g_xl);
    cudaGetSymbolAddress((void**)&eh, g_eh);
    cudaGetSymbolAddress((void**)&el, g_el);

    const int nx = N * DD, ne = K * DD;
    split_kernel<<<(nx + 255) / 256, 256>>>(x, xh, xl, nx);
    split_kernel<<<(ne + 255) / 256, 256>>>(e, eh, el, ne);
    esq_kernel<<<(K + 255) / 256, 256>>>(e, K);

    cudaFuncSetAttribute(vq_mma_kernel,
                         cudaFuncAttributeMaxDynamicSharedMemorySize, SMEM_BYTES);
    vq_mma_kernel<<<N / TILE_M, NT, SMEM_BYTES>>>(out, N, K);
}